// round 9
// baseline (speedup 1.0000x reference)
#include <cuda_runtime.h>
#include <cuda_fp16.h>

#define NSEG   8
#define KPTS   768
#define NMAPS  7
#define NPTS   (NSEG * KPTS)        // 6144
#define EPM    (KPTS * KPTS)        // 589824
#define ETOT   (NMAPS * EPM)        // 4128768

#define REPACK_BLOCKS (NMAPS * 1048576 / 8 / 256)   // 3584 (8 pixels/thread)
#define TABLE_BLOCKS  (NPTS / 256)                   // 24
#define SUBTILES      (NMAPS * KPTS * 3)             // 16128 (256 edges each)

// Scratch: channel-interleaved PAF in fp16: pixel -> half2(c0, c1), 28 MB
__device__ __half2 g_paf[NMAPS * 1048576];
// Packed per-point records: {x, y, paf.x, paf.y} (fp32 floats bit-cast into .z/.w)
__device__ int4 g_ptA[NPTS];   // endpoint sample as p1 (map seg(i):   x=0 sample == p1)
__device__ int4 g_ptB[NPTS];   // endpoint sample as p2 (map seg(i)-1: x=9 sample == p2)

__device__ __forceinline__ uint2 pack2(float a0, float b0, float a1, float b1) {
    __half2 h0 = __floats2half2_rn(a0, b0);
    __half2 h1 = __floats2half2_rn(a1, b1);
    return make_uint2(*(unsigned*)&h0, *(unsigned*)&h1);
}

// Repack (m, c, y, x) fp32 -> (m, y, x) half2(c0,c1); 8 pixels/thread for MLP.
// Tail blocks build the exact fp32 endpoint table.
__global__ void prep_kernel(const int* __restrict__ sk, const float* __restrict__ PAF) {
    if (blockIdx.x < REPACK_BLOCKS) {
        int t    = blockIdx.x * 256 + threadIdx.x;     // one t per 8 pixels
        int m    = t / (1048576 / 8);
        int pix8 = t - m * (1048576 / 8);
        const float4* c0p = (const float4*)(PAF + ((size_t)(2 * m)     << 20)) + pix8 * 2;
        const float4* c1p = (const float4*)(PAF + ((size_t)(2 * m + 1) << 20)) + pix8 * 2;
        float4 a0 = __ldg(&c0p[0]);
        float4 a1 = __ldg(&c0p[1]);
        float4 b0 = __ldg(&c1p[0]);
        float4 b1 = __ldg(&c1p[1]);
        uint4* dst = (uint4*)(g_paf + ((size_t)m << 20)) + pix8 * 2;
        uint2 p0 = pack2(a0.x, b0.x, a0.y, b0.y);
        uint2 p1 = pack2(a0.z, b0.z, a0.w, b0.w);
        uint2 p2 = pack2(a1.x, b1.x, a1.y, b1.y);
        uint2 p3 = pack2(a1.z, b1.z, a1.w, b1.w);
        dst[0] = make_uint4(p0.x, p0.y, p1.x, p1.y);
        dst[1] = make_uint4(p2.x, p2.y, p3.x, p3.y);
    } else {
        int i = (blockIdx.x - REPACK_BLOCKS) * 256 + threadIdx.x;   // < NPTS
        int s = i / KPTS;
        int x = __ldg(&sk[3 * i + 1]);
        int y = __ldg(&sk[3 * i + 2]);
        int pix = (y << 10) + x;                   // row = coord1, col = coord0
        float ax = 0.f, ay = 0.f, bx = 0.f, by = 0.f;
        if (s < NMAPS) {                           // point used as p1 on map s
            ax = __ldg(&PAF[((size_t)(2 * s)     << 20) + pix]);
            ay = __ldg(&PAF[((size_t)(2 * s + 1) << 20) + pix]);
        }
        if (s >= 1) {                              // point used as p2 on map s-1
            int m = s - 1;
            bx = __ldg(&PAF[((size_t)(2 * m)     << 20) + pix]);
            by = __ldg(&PAF[((size_t)(2 * m + 1) << 20) + pix]);
        }
        g_ptA[i] = make_int4(x, y, __float_as_int(ax), __float_as_int(ay));
        g_ptB[i] = make_int4(x, y, __float_as_int(bx), __float_as_int(by));
    }
}

// One 256-thread block per third of a (map m, p2-index a) row (R7 structure).
// Gathers use ld.global.cg: every access is an L1 miss anyway (4MB random set),
// so skip L1 allocation/eviction overhead and serve straight from L2.
__global__ __launch_bounds__(256) void paf_main_kernel(float* __restrict__ out) {
    int t   = blockIdx.x;
    int m   = t / (KPTS * 3);
    int rem = t - m * (KPTS * 3);
    int a   = rem / 3;
    int b   = (rem - a * 3) * 256 + threadIdx.x;

    int i2 = (m + 1) * KPTS + a;     // p2 global point id (broadcast across block)
    int i1 = m * KPTS + b;           // p1 global point id (per-lane, coalesced)

    int4 P2 = __ldg(&g_ptB[i2]);
    int4 P1 = __ldg(&g_ptA[i1]);
    int p2x = P2.x, p2y = P2.y;
    int p1x = P1.x, p1y = P1.y;

    int dx = p2x - p1x;
    int dy = p2y - p1y;
    float fdx = (float)dx, fdy = (float)dy;
    float R = sqrtf(fdx * fdx + fdy * fdy);

    const __half2* paf = g_paf + ((size_t)m << 20);

    // Interior samples x=1..8: pos = (p1*(9-x) + p2*x) // 9
    // n in [0, 9207]; floor(n/9) == (n*58255)>>19 exactly on that range.
    __half2 v[8];
    int nx = p1x * 9, ny = p1y * 9;
#pragma unroll
    for (int s = 0; s < 8; s++) {
        nx += dx; ny += dy;
        int lx = (nx * 58255) >> 19;
        int ly = (ny * 58255) >> 19;
        v[s] = __ldcg(&paf[(ly << 10) + lx]);
    }

    float sx = __int_as_float(P1.z) + __int_as_float(P2.z);   // exact x=0 / x=9 samples
    float sy = __int_as_float(P1.w) + __int_as_float(P2.w);
#pragma unroll
    for (int s = 0; s < 8; s++) {
        float2 f = __half22float2(v[s]);
        sx += f.x; sy += f.y;
    }

    float acc = fdx * sx + fdy * sy;
    float li = (R > 0.f) ? (acc / (10.f * R)) : 0.f;   // NaN (R==0) -> 0

    int idx = m * EPM + a * KPTS + b;
    // Output layout (float32): rows [i1 | i2 | li | R], each ETOT long
    out[idx]            = (float)i1;
    out[ETOT + idx]     = (float)i2;
    out[2 * ETOT + idx] = li;
    out[3 * ETOT + idx] = R;
}

extern "C" void kernel_launch(void* const* d_in, const int* in_sizes, int n_in,
                              void* d_out, int out_size) {
    const int*   sk  = (const int*)d_in[0];     // skeletons: (6144, 3) int32 [seg, x, y]
    const float* PAF = (const float*)d_in[1];   // (7, 2, 1024, 1024) float32
    float* out = (float*)d_out;

    cudaFuncSetAttribute(paf_main_kernel,
                         cudaFuncAttributePreferredSharedMemoryCarveout, 0);

    prep_kernel<<<REPACK_BLOCKS + TABLE_BLOCKS, 256>>>(sk, PAF);
    paf_main_kernel<<<SUBTILES, 256>>>(out);
}

// round 11
// speedup vs baseline: 1.0013x; 1.0013x over previous
#include <cuda_runtime.h>
#include <cuda_fp16.h>

#define NSEG   8
#define KPTS   768
#define NMAPS  7
#define NPTS   (NSEG * KPTS)        // 6144
#define EPM    (KPTS * KPTS)        // 589824
#define ETOT   (NMAPS * EPM)        // 4128768

#define REPACK_BLOCKS (NMAPS * 1048576 / 4 / 256)   // 7168 (4 pixels/thread, R7 form)
#define TABLE_BLOCKS  (NPTS / 256)                   // 24
#define SUBTILES      (NMAPS * KPTS * 3)             // 16128 (256 edges each)

// Scratch: channel-interleaved PAF in fp16: pixel -> half2(c0, c1), 28 MB
__device__ __half2 g_paf[NMAPS * 1048576];
// Packed per-point records: {x, y, paf.x, paf.y} (fp32 floats bit-cast into .z/.w)
__device__ int4 g_ptA[NPTS];   // endpoint sample as p1 (map seg(i):   x=0 sample == p1)
__device__ int4 g_ptB[NPTS];   // endpoint sample as p2 (map seg(i)-1: x=9 sample == p2)

// Repack (m, c, y, x) fp32 -> (m, y, x) half2(c0,c1); 4 pixels/thread, 16B stores.
// Tail blocks build the exact fp32 endpoint table.  (R7-proven configuration.)
__global__ void prep_kernel(const int* __restrict__ sk, const float* __restrict__ PAF) {
    if (blockIdx.x < REPACK_BLOCKS) {
        int t    = blockIdx.x * 256 + threadIdx.x;     // one t per 4 pixels
        int m    = t / (1048576 / 4);
        int pix4 = t - m * (1048576 / 4);
        const float4* c0p = (const float4*)(PAF + ((size_t)(2 * m)     << 20));
        const float4* c1p = (const float4*)(PAF + ((size_t)(2 * m + 1) << 20));
        float4 c0 = __ldg(&c0p[pix4]);
        float4 c1 = __ldg(&c1p[pix4]);
        __half2 h0 = __floats2half2_rn(c0.x, c1.x);
        __half2 h1 = __floats2half2_rn(c0.y, c1.y);
        __half2 h2 = __floats2half2_rn(c0.z, c1.z);
        __half2 h3 = __floats2half2_rn(c0.w, c1.w);
        uint4 pk;
        pk.x = *(unsigned*)&h0; pk.y = *(unsigned*)&h1;
        pk.z = *(unsigned*)&h2; pk.w = *(unsigned*)&h3;
        ((uint4*)(g_paf + ((size_t)m << 20)))[pix4] = pk;
    } else {
        int i = (blockIdx.x - REPACK_BLOCKS) * 256 + threadIdx.x;   // < NPTS
        int s = i / KPTS;
        int x = __ldg(&sk[3 * i + 1]);
        int y = __ldg(&sk[3 * i + 2]);
        int pix = (y << 10) + x;                   // row = coord1, col = coord0
        float ax = 0.f, ay = 0.f, bx = 0.f, by = 0.f;
        if (s < NMAPS) {                           // point used as p1 on map s
            ax = __ldg(&PAF[((size_t)(2 * s)     << 20) + pix]);
            ay = __ldg(&PAF[((size_t)(2 * s + 1) << 20) + pix]);
        }
        if (s >= 1) {                              // point used as p2 on map s-1
            int m = s - 1;
            bx = __ldg(&PAF[((size_t)(2 * m)     << 20) + pix]);
            by = __ldg(&PAF[((size_t)(2 * m + 1) << 20) + pix]);
        }
        g_ptA[i] = make_int4(x, y, __float_as_int(ax), __float_as_int(ay));
        g_ptB[i] = make_int4(x, y, __float_as_int(bx), __float_as_int(by));
    }
}

// Persistent grid: exactly one wave of blocks, grid-stride over 256-edge sub-tiles.
// Removes wave quantization + last-wave SM spread. Inner body identical to R9.
__global__ __launch_bounds__(256) void paf_main_kernel(float* __restrict__ out, int nblocks) {
    for (int t = blockIdx.x; t < SUBTILES; t += nblocks) {
        int m   = t / (KPTS * 3);
        int rem = t - m * (KPTS * 3);
        int a   = rem / 3;
        int b   = (rem - a * 3) * 256 + threadIdx.x;

        int i2 = (m + 1) * KPTS + a;     // p2 global point id (broadcast across block)
        int i1 = m * KPTS + b;           // p1 global point id (per-lane, coalesced)

        int4 P2 = __ldg(&g_ptB[i2]);
        int4 P1 = __ldg(&g_ptA[i1]);
        int p1x = P1.x, p1y = P1.y;

        int dx = P2.x - p1x;
        int dy = P2.y - p1y;
        float fdx = (float)dx, fdy = (float)dy;
        float R = sqrtf(fdx * fdx + fdy * fdy);

        const __half2* paf = g_paf + ((size_t)m << 20);

        // Interior samples x=1..8: pos = (p1*(9-x) + p2*x) // 9
        // n in [0, 9207]; floor(n/9) == (n*58255)>>19 exactly on that range.
        __half2 v[8];
        int nx = p1x * 9, ny = p1y * 9;
#pragma unroll
        for (int s = 0; s < 8; s++) {
            nx += dx; ny += dy;
            int lx = (nx * 58255) >> 19;
            int ly = (ny * 58255) >> 19;
            v[s] = __ldcg(&paf[(ly << 10) + lx]);
        }

        float sx = __int_as_float(P1.z) + __int_as_float(P2.z);   // exact x=0 / x=9 samples
        float sy = __int_as_float(P1.w) + __int_as_float(P2.w);
#pragma unroll
        for (int s = 0; s < 8; s++) {
            float2 f = __half22float2(v[s]);
            sx += f.x; sy += f.y;
        }

        float acc = fdx * sx + fdy * sy;
        float li = (R > 0.f) ? (acc / (10.f * R)) : 0.f;   // NaN (R==0) -> 0

        int idx = m * EPM + a * KPTS + b;
        // Output layout (float32): rows [i1 | i2 | li | R], each ETOT long
        out[idx]            = (float)i1;
        out[ETOT + idx]     = (float)i2;
        out[2 * ETOT + idx] = li;
        out[3 * ETOT + idx] = R;
    }
}

extern "C" void kernel_launch(void* const* d_in, const int* in_sizes, int n_in,
                              void* d_out, int out_size) {
    const int*   sk  = (const int*)d_in[0];     // skeletons: (6144, 3) int32 [seg, x, y]
    const float* PAF = (const float*)d_in[1];   // (7, 2, 1024, 1024) float32
    float* out = (float*)d_out;

    int nSM = 148;
    cudaDeviceGetAttribute(&nSM, cudaDevAttrMultiProcessorCount, 0);
    int nblocks = 8 * nSM;   // one full resident wave (32 regs, 256 thr -> 8 blocks/SM)

    cudaFuncSetAttribute(paf_main_kernel,
                         cudaFuncAttributePreferredSharedMemoryCarveout, 0);

    prep_kernel<<<REPACK_BLOCKS + TABLE_BLOCKS, 256>>>(sk, PAF);
    paf_main_kernel<<<nblocks, 256>>>(out, nblocks);
}